// round 1
// baseline (speedup 1.0000x reference)
#include <cuda_runtime.h>
#include <math.h>

#define BB 64
#define TT 512
#define II 256
#define HH 512
#define CC 128

#define NBLK 128
#define NTHR 256
#define CHUNK 128
#define INPITCH 132   // 128 + 4 pad floats: conflict-free float4 rows

// ---------------- scratch (static device globals; no allocation) ----------------
__device__ float g_hseq0[(size_t)BB * TT * HH];   // layer0 output sequence [B,T,H]
__device__ float g_h1last[BB * HH];               // layer1 final hidden
__device__ float g_hbuf[2][BB * HH];              // h ping-pong
__device__ unsigned g_bar_count;                  // zero-init
__device__ volatile unsigned g_bar_gen;           // zero-init

// ---------------- helpers ----------------
__device__ __forceinline__ void cp_async16_cg(void* smem_dst, const void* gsrc) {
    unsigned s = (unsigned)__cvta_generic_to_shared(smem_dst);
    asm volatile("cp.async.cg.shared.global [%0], [%1], 16;\n" :: "r"(s), "l"(gsrc) : "memory");
}
__device__ __forceinline__ void cp_commit() {
    asm volatile("cp.async.commit_group;\n" ::: "memory");
}
template <int N>
__device__ __forceinline__ void cp_wait() {
    asm volatile("cp.async.wait_group %0;\n" :: "n"(N) : "memory");
}

// software grid barrier: all NBLK blocks are co-resident (1 CTA/SM by smem).
__device__ __forceinline__ void grid_barrier() {
    __threadfence();          // publish this thread's writes
    __syncthreads();
    if (threadIdx.x == 0) {
        unsigned gen = g_bar_gen;
        unsigned arrived = atomicAdd(&g_bar_count, 1u);
        if (arrived == NBLK - 1) {
            g_bar_count = 0;
            __threadfence();
            g_bar_gen = gen + 1;   // release
        } else {
            while (g_bar_gen == gen) { }  // volatile spin (L2, bypasses L1)
        }
        __threadfence();          // acquire
    }
    __syncthreads();
}

__device__ __forceinline__ float sigmoidf_(float x) {
    return 1.0f / (1.0f + __expf(-x));
}

// ---------------- persistent LSTM layer kernel ----------------
// Each block owns 4 h-columns -> 16 gate rows (i,f,g,o for those columns).
// SMEM: W_s[16][Ktot] (W_ih|W_hh concatenated), double-buffered input staging,
// bias. c-state lives in a register per thread. One grid barrier per step.
__global__ void __launch_bounds__(NTHR, 1) lstm_rec_kernel(
    const float* __restrict__ xin,   // [B, T, Kin]
    const float* __restrict__ W_ih,  // [4H, Kin]
    const float* __restrict__ W_hh,  // [4H, H]
    const float* __restrict__ b_ih,  // [4H]
    const float* __restrict__ b_hh,  // [4H]
    const float* __restrict__ h0,    // [B, H] (layer slice)
    const float* __restrict__ c0,    // [B, H] (layer slice)
    float* __restrict__ hseq_out,    // [B, T, H] or nullptr
    float* __restrict__ hlast_out,   // [B, H]   or nullptr
    int Kin)
{
    const int tid = threadIdx.x;
    const int blk = blockIdx.x;
    const int Ktot = Kin + HH;
    const int r  = tid & 63;   // batch row
    const int j4 = tid >> 6;   // h-column within block (0..3)
    const int col = blk * 4 + j4;

    extern __shared__ float smem[];
    float* W_s    = smem;                          // 16 * Ktot
    float* in_s   = smem + 16 * Ktot;              // 2 * 64 * INPITCH
    float* bias_s = in_s + 2 * 64 * INPITCH;       // 16

    // --- load fused weight slice [W_ih | W_hh] for our 16 gate rows ---
    for (int idx = tid; idx < 16 * Ktot; idx += NTHR) {
        int l = idx / Ktot;
        int k = idx - l * Ktot;
        int g = (l >> 2) * HH + blk * 4 + (l & 3);   // global gate row
        W_s[idx] = (k < Kin) ? W_ih[(size_t)g * Kin + k]
                             : W_hh[(size_t)g * HH + (k - Kin)];
    }
    if (tid < 16) {
        int g = (tid >> 2) * HH + blk * 4 + (tid & 3);
        bias_s[tid] = b_ih[g] + b_hh[g];
    }

    // --- init state ---
    float c_reg = c0[r * HH + col];
    g_hbuf[0][r * HH + col] = h0[r * HH + col];
    grid_barrier();   // h0 fully published before step 0

    const int nch = Ktot / CHUNK;

    for (int t = 0; t < TT; t++) {
        const int p = t & 1;
        const float* hprev = g_hbuf[p];

        float acc0 = bias_s[j4];
        float acc1 = bias_s[4 + j4];
        float acc2 = bias_s[8 + j4];
        float acc3 = bias_s[12 + j4];

        // stage one 64xCHUNK chunk of concat(x_t, h_prev) into buffer b
        auto stage = [&](int ch, int b) {
            const int kbase = ch * CHUNK;
            float* dst = in_s + b * 64 * INPITCH;
            #pragma unroll
            for (int i = 0; i < (64 * CHUNK / 4) / NTHR; i++) {  // 8
                int idx = tid + i * NTHR;
                int row = idx >> 5;          // 32 float4 per row
                int k4  = (idx & 31) << 2;
                int kk  = kbase + k4;
                const float* src = (kk < Kin)
                    ? (xin + ((size_t)row * TT + t) * Kin + kk)
                    : (hprev + row * HH + (kk - Kin));
                cp_async16_cg(dst + row * INPITCH + k4, src);
            }
            cp_commit();
        };

        stage(0, 0);
        for (int ch = 0; ch < nch; ch++) {
            if (ch + 1 < nch) {
                stage(ch + 1, (ch + 1) & 1);
                cp_wait<1>();
            } else {
                cp_wait<0>();
            }
            __syncthreads();

            const float* ins = in_s + (ch & 1) * 64 * INPITCH + r * INPITCH;
            const float* w0 = W_s + ( 0 + j4) * Ktot + ch * CHUNK;
            const float* w1 = W_s + ( 4 + j4) * Ktot + ch * CHUNK;
            const float* w2 = W_s + ( 8 + j4) * Ktot + ch * CHUNK;
            const float* w3 = W_s + (12 + j4) * Ktot + ch * CHUNK;

            #pragma unroll 8
            for (int k = 0; k < CHUNK; k += 4) {
                float4 xv = *(const float4*)(ins + k);
                float4 a  = *(const float4*)(w0 + k);
                float4 b2 = *(const float4*)(w1 + k);
                float4 c2 = *(const float4*)(w2 + k);
                float4 d2 = *(const float4*)(w3 + k);
                acc0 += xv.x*a.x  + xv.y*a.y  + xv.z*a.z  + xv.w*a.w;
                acc1 += xv.x*b2.x + xv.y*b2.y + xv.z*b2.z + xv.w*b2.w;
                acc2 += xv.x*c2.x + xv.y*c2.y + xv.z*c2.z + xv.w*c2.w;
                acc3 += xv.x*d2.x + xv.y*d2.y + xv.z*d2.z + xv.w*d2.w;
            }
            __syncthreads();   // protect staging buffer reuse
        }

        // gates -> state update (PyTorch order i, f, g, o)
        float iv = sigmoidf_(acc0);
        float fv = sigmoidf_(acc1);
        float gv = tanhf(acc2);
        float ov = sigmoidf_(acc3);
        c_reg = fv * c_reg + iv * gv;
        float hv = ov * tanhf(c_reg);

        g_hbuf[p ^ 1][r * HH + col] = hv;
        if (hseq_out)  hseq_out[((size_t)r * TT + t) * HH + col] = hv;
        if (hlast_out && t == TT - 1) hlast_out[r * HH + col] = hv;

        grid_barrier();
    }
}

// ---------------- final linear head ----------------
__global__ void fc_kernel(const float* __restrict__ h,   // [B,H]
                          const float* __restrict__ W,   // [C,H]
                          const float* __restrict__ b,   // [C]
                          float* __restrict__ out)       // [B,C]
{
    int idx = blockIdx.x * blockDim.x + threadIdx.x;   // 8192
    int r = idx >> 7;
    int c = idx & 127;
    const float* hr = h + r * HH;
    const float* wc = W + c * HH;
    float acc = b[c];
    #pragma unroll 4
    for (int k = 0; k < HH; k += 4) {
        float4 hv = *(const float4*)(hr + k);
        float4 wv = *(const float4*)(wc + k);
        acc += hv.x*wv.x + hv.y*wv.y + hv.z*wv.z + hv.w*wv.w;
    }
    out[idx] = acc;
}

// ---------------- launch ----------------
extern "C" void kernel_launch(void* const* d_in, const int* in_sizes, int n_in,
                              void* d_out, int out_size) {
    const float* x     = (const float*)d_in[0];
    const float* h0    = (const float*)d_in[1];
    const float* c0    = (const float*)d_in[2];
    const float* W_ih0 = (const float*)d_in[3];
    const float* W_hh0 = (const float*)d_in[4];
    const float* b_ih0 = (const float*)d_in[5];
    const float* b_hh0 = (const float*)d_in[6];
    const float* W_ih1 = (const float*)d_in[7];
    const float* W_hh1 = (const float*)d_in[8];
    const float* b_ih1 = (const float*)d_in[9];
    const float* b_hh1 = (const float*)d_in[10];
    const float* W_fc  = (const float*)d_in[11];
    const float* b_fc  = (const float*)d_in[12];

    float *hseq0, *h1last;
    cudaGetSymbolAddress((void**)&hseq0,  g_hseq0);
    cudaGetSymbolAddress((void**)&h1last, g_h1last);

    const int smem_l0 = (16 * (II + HH) + 2 * 64 * INPITCH + 16) * sizeof(float);
    const int smem_l1 = (16 * (HH + HH) + 2 * 64 * INPITCH + 16) * sizeof(float);
    cudaFuncSetAttribute((const void*)lstm_rec_kernel,
                         cudaFuncAttributeMaxDynamicSharedMemorySize, smem_l1);

    // layer 0: input = x [B,T,I]; writes full hidden sequence
    lstm_rec_kernel<<<NBLK, NTHR, smem_l0>>>(
        x, W_ih0, W_hh0, b_ih0, b_hh0,
        h0 + 0 * BB * HH, c0 + 0 * BB * HH,
        hseq0, nullptr, II);

    // layer 1: input = layer0 hidden sequence [B,T,H]; keeps only last h
    lstm_rec_kernel<<<NBLK, NTHR, smem_l1>>>(
        hseq0, W_ih1, W_hh1, b_ih1, b_hh1,
        h0 + 1 * BB * HH, c0 + 1 * BB * HH,
        nullptr, h1last, HH);

    fc_kernel<<<(BB * CC) / NTHR, NTHR>>>(h1last, W_fc, b_fc, (float*)d_out);
}

// round 2
// speedup vs baseline: 1.0005x; 1.0005x over previous
#include <cuda_runtime.h>
#include <math.h>

#define BB 64
#define TT 512
#define II 256
#define HH 512
#define CC 128

#define NBLK 128
#define NTHR 256
#define CHUNK 128
#define INPITCH 132   // 128 + 4 pad floats: conflict-free float4 rows

// ---------------- scratch (static device globals; no allocation) ----------------
__device__ float g_hseq0[(size_t)BB * TT * HH];   // layer0 output sequence [B,T,H]
__device__ float g_h1last[BB * HH];               // layer1 final hidden
__device__ float g_hbuf[2][BB * HH];              // h ping-pong
__device__ unsigned g_bar_count;                  // zero-init
__device__ volatile unsigned g_bar_gen;           // zero-init

// ---------------- helpers ----------------
__device__ __forceinline__ void cp_async16_cg(void* smem_dst, const void* gsrc) {
    unsigned s = (unsigned)__cvta_generic_to_shared(smem_dst);
    asm volatile("cp.async.cg.shared.global [%0], [%1], 16;\n" :: "r"(s), "l"(gsrc) : "memory");
}
__device__ __forceinline__ void cp_commit() {
    asm volatile("cp.async.commit_group;\n" ::: "memory");
}
template <int N>
__device__ __forceinline__ void cp_wait() {
    asm volatile("cp.async.wait_group %0;\n" :: "n"(N) : "memory");
}

// software grid barrier: all NBLK blocks are co-resident (1 CTA/SM by smem).
__device__ __forceinline__ void grid_barrier() {
    __threadfence();          // publish this thread's writes
    __syncthreads();
    if (threadIdx.x == 0) {
        unsigned gen = g_bar_gen;
        unsigned arrived = atomicAdd(&g_bar_count, 1u);
        if (arrived == NBLK - 1) {
            g_bar_count = 0;
            __threadfence();
            g_bar_gen = gen + 1;   // release
        } else {
            while (g_bar_gen == gen) { }  // volatile spin (L2, bypasses L1)
        }
        __threadfence();          // acquire
    }
    __syncthreads();
}

__device__ __forceinline__ float sigmoidf_(float x) {
    return 1.0f / (1.0f + __expf(-x));
}

// ---------------- persistent LSTM layer kernel ----------------
// Each block owns 4 h-columns -> 16 gate rows (i,f,g,o for those columns).
// SMEM: W_s[16][Ktot] (W_ih|W_hh concatenated), double-buffered input staging,
// bias. c-state lives in a register per thread. One grid barrier per step.
__global__ void __launch_bounds__(NTHR, 1) lstm_rec_kernel(
    const float* __restrict__ xin,   // [B, T, Kin]
    const float* __restrict__ W_ih,  // [4H, Kin]
    const float* __restrict__ W_hh,  // [4H, H]
    const float* __restrict__ b_ih,  // [4H]
    const float* __restrict__ b_hh,  // [4H]
    const float* __restrict__ h0,    // [B, H] (layer slice)
    const float* __restrict__ c0,    // [B, H] (layer slice)
    float* __restrict__ hseq_out,    // [B, T, H] or nullptr
    float* __restrict__ hlast_out,   // [B, H]   or nullptr
    int Kin)
{
    const int tid = threadIdx.x;
    const int blk = blockIdx.x;
    const int Ktot = Kin + HH;
    const int r  = tid & 63;   // batch row
    const int j4 = tid >> 6;   // h-column within block (0..3)
    const int col = blk * 4 + j4;

    extern __shared__ float smem[];
    float* W_s    = smem;                          // 16 * Ktot
    float* in_s   = smem + 16 * Ktot;              // 2 * 64 * INPITCH
    float* bias_s = in_s + 2 * 64 * INPITCH;       // 16

    // --- load fused weight slice [W_ih | W_hh] for our 16 gate rows ---
    for (int idx = tid; idx < 16 * Ktot; idx += NTHR) {
        int l = idx / Ktot;
        int k = idx - l * Ktot;
        int g = (l >> 2) * HH + blk * 4 + (l & 3);   // global gate row
        W_s[idx] = (k < Kin) ? W_ih[(size_t)g * Kin + k]
                             : W_hh[(size_t)g * HH + (k - Kin)];
    }
    if (tid < 16) {
        int g = (tid >> 2) * HH + blk * 4 + (tid & 3);
        bias_s[tid] = b_ih[g] + b_hh[g];
    }

    // --- init state ---
    float c_reg = c0[r * HH + col];
    g_hbuf[0][r * HH + col] = h0[r * HH + col];
    grid_barrier();   // h0 fully published before step 0

    const int nch = Ktot / CHUNK;

    for (int t = 0; t < TT; t++) {
        const int p = t & 1;
        const float* hprev = g_hbuf[p];

        float acc0 = bias_s[j4];
        float acc1 = bias_s[4 + j4];
        float acc2 = bias_s[8 + j4];
        float acc3 = bias_s[12 + j4];

        // stage one 64xCHUNK chunk of concat(x_t, h_prev) into buffer b
        auto stage = [&](int ch, int b) {
            const int kbase = ch * CHUNK;
            float* dst = in_s + b * 64 * INPITCH;
            #pragma unroll
            for (int i = 0; i < (64 * CHUNK / 4) / NTHR; i++) {  // 8
                int idx = tid + i * NTHR;
                int row = idx >> 5;          // 32 float4 per row
                int k4  = (idx & 31) << 2;
                int kk  = kbase + k4;
                const float* src = (kk < Kin)
                    ? (xin + ((size_t)row * TT + t) * Kin + kk)
                    : (hprev + row * HH + (kk - Kin));
                cp_async16_cg(dst + row * INPITCH + k4, src);
            }
            cp_commit();
        };

        stage(0, 0);
        for (int ch = 0; ch < nch; ch++) {
            if (ch + 1 < nch) {
                stage(ch + 1, (ch + 1) & 1);
                cp_wait<1>();
            } else {
                cp_wait<0>();
            }
            __syncthreads();

            const float* ins = in_s + (ch & 1) * 64 * INPITCH + r * INPITCH;
            const float* w0 = W_s + ( 0 + j4) * Ktot + ch * CHUNK;
            const float* w1 = W_s + ( 4 + j4) * Ktot + ch * CHUNK;
            const float* w2 = W_s + ( 8 + j4) * Ktot + ch * CHUNK;
            const float* w3 = W_s + (12 + j4) * Ktot + ch * CHUNK;

            #pragma unroll 8
            for (int k = 0; k < CHUNK; k += 4) {
                float4 xv = *(const float4*)(ins + k);
                float4 a  = *(const float4*)(w0 + k);
                float4 b2 = *(const float4*)(w1 + k);
                float4 c2 = *(const float4*)(w2 + k);
                float4 d2 = *(const float4*)(w3 + k);
                acc0 += xv.x*a.x  + xv.y*a.y  + xv.z*a.z  + xv.w*a.w;
                acc1 += xv.x*b2.x + xv.y*b2.y + xv.z*b2.z + xv.w*b2.w;
                acc2 += xv.x*c2.x + xv.y*c2.y + xv.z*c2.z + xv.w*c2.w;
                acc3 += xv.x*d2.x + xv.y*d2.y + xv.z*d2.z + xv.w*d2.w;
            }
            __syncthreads();   // protect staging buffer reuse
        }

        // gates -> state update (PyTorch order i, f, g, o)
        float iv = sigmoidf_(acc0);
        float fv = sigmoidf_(acc1);
        float gv = tanhf(acc2);
        float ov = sigmoidf_(acc3);
        c_reg = fv * c_reg + iv * gv;
        float hv = ov * tanhf(c_reg);

        g_hbuf[p ^ 1][r * HH + col] = hv;
        if (hseq_out)  hseq_out[((size_t)r * TT + t) * HH + col] = hv;
        if (hlast_out && t == TT - 1) hlast_out[r * HH + col] = hv;

        grid_barrier();
    }
}

// ---------------- final linear head ----------------
__global__ void fc_kernel(const float* __restrict__ h,   // [B,H]
                          const float* __restrict__ W,   // [C,H]
                          const float* __restrict__ b,   // [C]
                          float* __restrict__ out)       // [B,C]
{
    int idx = blockIdx.x * blockDim.x + threadIdx.x;   // 8192
    int r = idx >> 7;
    int c = idx & 127;
    const float* hr = h + r * HH;
    const float* wc = W + c * HH;
    float acc = b[c];
    #pragma unroll 4
    for (int k = 0; k < HH; k += 4) {
        float4 hv = *(const float4*)(hr + k);
        float4 wv = *(const float4*)(wc + k);
        acc += hv.x*wv.x + hv.y*wv.y + hv.z*wv.z + hv.w*wv.w;
    }
    out[idx] = acc;
}

// ---------------- launch ----------------
extern "C" void kernel_launch(void* const* d_in, const int* in_sizes, int n_in,
                              void* d_out, int out_size) {
    const float* x     = (const float*)d_in[0];
    const float* h0    = (const float*)d_in[1];
    const float* c0    = (const float*)d_in[2];
    const float* W_ih0 = (const float*)d_in[3];
    const float* W_hh0 = (const float*)d_in[4];
    const float* b_ih0 = (const float*)d_in[5];
    const float* b_hh0 = (const float*)d_in[6];
    const float* W_ih1 = (const float*)d_in[7];
    const float* W_hh1 = (const float*)d_in[8];
    const float* b_ih1 = (const float*)d_in[9];
    const float* b_hh1 = (const float*)d_in[10];
    const float* W_fc  = (const float*)d_in[11];
    const float* b_fc  = (const float*)d_in[12];

    float *hseq0, *h1last;
    cudaGetSymbolAddress((void**)&hseq0,  g_hseq0);
    cudaGetSymbolAddress((void**)&h1last, g_h1last);

    const int smem_l0 = (16 * (II + HH) + 2 * 64 * INPITCH + 16) * sizeof(float);
    const int smem_l1 = (16 * (HH + HH) + 2 * 64 * INPITCH + 16) * sizeof(float);
    cudaFuncSetAttribute((const void*)lstm_rec_kernel,
                         cudaFuncAttributeMaxDynamicSharedMemorySize, smem_l1);

    // layer 0: input = x [B,T,I]; writes full hidden sequence
    lstm_rec_kernel<<<NBLK, NTHR, smem_l0>>>(
        x, W_ih0, W_hh0, b_ih0, b_hh0,
        h0 + 0 * BB * HH, c0 + 0 * BB * HH,
        hseq0, nullptr, II);

    // layer 1: input = layer0 hidden sequence [B,T,H]; keeps only last h
    lstm_rec_kernel<<<NBLK, NTHR, smem_l1>>>(
        hseq0, W_ih1, W_hh1, b_ih1, b_hh1,
        h0 + 1 * BB * HH, c0 + 1 * BB * HH,
        nullptr, h1last, HH);

    fc_kernel<<<(BB * CC) / NTHR, NTHR>>>(h1last, W_fc, b_fc, (float*)d_out);
}

// round 3
// speedup vs baseline: 1.1431x; 1.1425x over previous
#include <cuda_runtime.h>
#include <math.h>

#define BB 64
#define TT 512
#define II 256
#define HH 512
#define CC 128

#define NBLK 128
#define NTHR 512
#define CHUNK 128
#define INPITCH 132   // 128 + 4 pad floats

typedef unsigned long long ull;

// ---------------- scratch (static device globals; no allocation) ----------------
__device__ float g_hseq0[(size_t)BB * TT * HH];   // layer0 output sequence [B,T,H]
__device__ float g_h1last[BB * HH];               // layer1 final hidden
__device__ float g_hbuf[2][BB * HH];              // h ping-pong
__device__ unsigned g_ctr;                        // zero-init; self-resets each layer

// ---------------- helpers ----------------
__device__ __forceinline__ void cp_async16_cg(void* smem_dst, const void* gsrc) {
    unsigned s = (unsigned)__cvta_generic_to_shared(smem_dst);
    asm volatile("cp.async.cg.shared.global [%0], [%1], 16;\n" :: "r"(s), "l"(gsrc) : "memory");
}
__device__ __forceinline__ void cp_commit() {
    asm volatile("cp.async.commit_group;\n" ::: "memory");
}
template <int N>
__device__ __forceinline__ void cp_wait() {
    asm volatile("cp.async.wait_group %0;\n" :: "n"(N) : "memory");
}

// packed fp32x2 FMA (Blackwell FFMA2 — only reachable via PTX)
__device__ __forceinline__ ull ffma2(ull a, ull b, ull c) {
    ull d;
    asm("fma.rn.f32x2 %0, %1, %2, %3;" : "=l"(d) : "l"(a), "l"(b), "l"(c));
    return d;
}
__device__ __forceinline__ float2 unpack2(ull v) {
    float2 f;
    asm("mov.b64 {%0, %1}, %2;" : "=f"(f.x), "=f"(f.y) : "l"(v));
    return f;
}

// grid barrier primitives: monotone counter, release-arrive / acquire-poll.
__device__ __forceinline__ void bar_arrive(unsigned* ctr, unsigned finalv) {
    unsigned old;
    asm volatile("atom.release.gpu.global.add.u32 %0, [%1], %2;"
                 : "=r"(old) : "l"(ctr), "r"(1u) : "memory");
    if (old == finalv - 1u) {  // very last arrival of this layer: reset for graph replay
        asm volatile("st.relaxed.gpu.global.u32 [%0], %1;" :: "l"(ctr), "r"(0u) : "memory");
    }
}
__device__ __forceinline__ void bar_wait(unsigned* ctr, unsigned target) {
    unsigned v;
    do {
        asm volatile("ld.acquire.gpu.global.u32 %0, [%1];" : "=r"(v) : "l"(ctr) : "memory");
    } while (v < target);
}

__device__ __forceinline__ float sigmoidf_(float x) {
    return 1.0f / (1.0f + __expf(-x));
}

// ---------------- persistent LSTM layer kernel ----------------
// Block owns 4 h-columns -> 16 gate rows. 512 threads = (64 rows) x (4 cols) x (2 k-halves).
// Weights resident in SMEM for all T steps; c-state in registers; h ping-pongs via L2.
// x-chunks (no h dependency) are computed while waiting on the grid barrier.
__global__ void __launch_bounds__(NTHR, 1) lstm_rec_kernel(
    const float* __restrict__ xin,   // [B, T, Kin]
    const float* __restrict__ W_ih,  // [4H, Kin]
    const float* __restrict__ W_hh,  // [4H, H]
    const float* __restrict__ b_ih,  // [4H]
    const float* __restrict__ b_hh,  // [4H]
    const float* __restrict__ h0,    // [B, H]
    const float* __restrict__ c0,    // [B, H]
    float* __restrict__ hseq_out,    // [B, T, H] or nullptr
    float* __restrict__ hlast_out,   // [B, H]   or nullptr
    int Kin)
{
    const int tid = threadIdx.x;
    const int blk = blockIdx.x;
    const int Ktot = Kin + HH;
    const int r   = tid & 63;          // batch row
    const int j4  = (tid >> 6) & 3;    // h-column within block
    const int kh  = tid >> 8;          // k-half (0/1)
    const int col = blk * 4 + j4;
    const int khoff = kh * 64;
    const unsigned finalv = (unsigned)(NBLK * (TT + 1));

    extern __shared__ float smem[];
    float* W_s    = smem;                          // 16 * Ktot
    float* in_s   = W_s + 16 * Ktot;               // 2 * 64 * INPITCH
    float* pex    = in_s + 2 * 64 * INPITCH;       // 256 * 4 partial exchange
    float* bias_s = pex + 1024;                    // 16

    // --- load fused weight slice [W_ih | W_hh] for our 16 gate rows ---
    for (int idx = tid; idx < 16 * Ktot; idx += NTHR) {
        int l = idx / Ktot;
        int k = idx - l * Ktot;
        int g = (l >> 2) * HH + blk * 4 + (l & 3);
        W_s[idx] = (k < Kin) ? W_ih[(size_t)g * Kin + k]
                             : W_hh[(size_t)g * HH + (k - Kin)];
    }
    if (tid < 16) {
        int g = (tid >> 2) * HH + blk * 4 + (tid & 3);
        bias_s[tid] = b_ih[g] + b_hh[g];
    }

    // --- init state; publish h0 slice ---
    float c_reg = 0.0f;
    if (kh == 0) {
        c_reg = c0[r * HH + col];
        g_hbuf[0][r * HH + col] = h0[r * HH + col];
    }
    __syncthreads();
    if (tid == 0) bar_arrive(&g_ctr, finalv);

    const int nch = Ktot / CHUNK;
    const int nx  = Kin / CHUNK;   // pure-x chunks (no barrier dependency)

    for (int t = 0; t < TT; t++) {
        const int p = t & 1;
        const float* hprev = g_hbuf[p];

        auto stage = [&](int ch) {
            const int kbase = ch * CHUNK;
            float* dst = in_s + (ch & 1) * 64 * INPITCH;
            #pragma unroll
            for (int i = 0; i < 4; i++) {          // 2048 float4 / 512 thr
                int idx = tid + i * NTHR;
                int row = idx >> 5;
                int k4  = (idx & 31) << 2;
                int kk  = kbase + k4;
                const float* src = (kk < Kin)
                    ? (xin + ((size_t)row * TT + t) * Kin + kk)
                    : (hprev + row * HH + (kk - Kin));
                cp_async16_cg(dst + row * INPITCH + k4, src);
            }
            cp_commit();
        };

        ull acc0 = 0ull, acc1 = 0ull, acc2 = 0ull, acc3 = 0ull;

        stage(0);
        for (int ch = 0; ch < nch; ch++) {
            if (ch + 1 < nch) {
                if (ch + 1 == nx) {   // about to stage first h-chunk: need h published
                    if (tid == 0) bar_wait(&g_ctr, (unsigned)((t + 1) * NBLK));
                    __syncthreads();
                }
                stage(ch + 1);
                cp_wait<1>();
            } else {
                cp_wait<0>();
            }
            __syncthreads();

            const float* ins = in_s + (ch & 1) * 64 * INPITCH + r * INPITCH + khoff;
            const float* w0 = W_s + ( 0 + j4) * Ktot + ch * CHUNK + khoff;
            const float* w1 = W_s + ( 4 + j4) * Ktot + ch * CHUNK + khoff;
            const float* w2 = W_s + ( 8 + j4) * Ktot + ch * CHUNK + khoff;
            const float* w3 = W_s + (12 + j4) * Ktot + ch * CHUNK + khoff;

            #pragma unroll
            for (int k = 0; k < 64; k += 4) {
                ulonglong2 xv = *(const ulonglong2*)(ins + k);
                ulonglong2 wa = *(const ulonglong2*)(w0 + k);
                ulonglong2 wb = *(const ulonglong2*)(w1 + k);
                ulonglong2 wc = *(const ulonglong2*)(w2 + k);
                ulonglong2 wd = *(const ulonglong2*)(w3 + k);
                acc0 = ffma2(xv.x, wa.x, acc0);  acc0 = ffma2(xv.y, wa.y, acc0);
                acc1 = ffma2(xv.x, wb.x, acc1);  acc1 = ffma2(xv.y, wb.y, acc1);
                acc2 = ffma2(xv.x, wc.x, acc2);  acc2 = ffma2(xv.y, wc.y, acc2);
                acc3 = ffma2(xv.x, wd.x, acc3);  acc3 = ffma2(xv.y, wd.y, acc3);
            }
            __syncthreads();   // staging buffer reuse guard
        }

        // --- combine k-halves, gates, state update ---
        float2 f0 = unpack2(acc0), f1 = unpack2(acc1), f2 = unpack2(acc2), f3 = unpack2(acc3);
        float s0 = f0.x + f0.y, s1 = f1.x + f1.y, s2 = f2.x + f2.y, s3 = f3.x + f3.y;

        if (kh == 1) {
            float4 v = make_float4(s0, s1, s2, s3);
            *(float4*)(pex + (tid & 255) * 4) = v;
        }
        __syncthreads();
        if (kh == 0) {
            float4 pp = *(const float4*)(pex + tid * 4);
            float a0 = s0 + pp.x + bias_s[j4];
            float a1 = s1 + pp.y + bias_s[4 + j4];
            float a2 = s2 + pp.z + bias_s[8 + j4];
            float a3 = s3 + pp.w + bias_s[12 + j4];
            float iv = sigmoidf_(a0);
            float fv = sigmoidf_(a1);
            float gv = tanhf(a2);
            float ov = sigmoidf_(a3);
            c_reg = fv * c_reg + iv * gv;
            float hv = ov * tanhf(c_reg);

            g_hbuf[p ^ 1][r * HH + col] = hv;
            if (hseq_out)  hseq_out[((size_t)r * TT + t) * HH + col] = hv;
            if (hlast_out && t == TT - 1) hlast_out[r * HH + col] = hv;
        }
        __syncthreads();
        if (tid == 0) bar_arrive(&g_ctr, finalv);
    }
}

// ---------------- final linear head ----------------
__global__ void fc_kernel(const float* __restrict__ h,   // [B,H]
                          const float* __restrict__ W,   // [C,H]
                          const float* __restrict__ b,   // [C]
                          float* __restrict__ out)       // [B,C]
{
    int idx = blockIdx.x * blockDim.x + threadIdx.x;   // 8192
    int r = idx >> 7;
    int c = idx & 127;
    const float* hr = h + r * HH;
    const float* wc = W + c * HH;
    float acc = b[c];
    #pragma unroll 4
    for (int k = 0; k < HH; k += 4) {
        float4 hv = *(const float4*)(hr + k);
        float4 wv = *(const float4*)(wc + k);
        acc += hv.x*wv.x + hv.y*wv.y + hv.z*wv.z + hv.w*wv.w;
    }
    out[idx] = acc;
}

// ---------------- launch ----------------
extern "C" void kernel_launch(void* const* d_in, const int* in_sizes, int n_in,
                              void* d_out, int out_size) {
    const float* x     = (const float*)d_in[0];
    const float* h0    = (const float*)d_in[1];
    const float* c0    = (const float*)d_in[2];
    const float* W_ih0 = (const float*)d_in[3];
    const float* W_hh0 = (const float*)d_in[4];
    const float* b_ih0 = (const float*)d_in[5];
    const float* b_hh0 = (const float*)d_in[6];
    const float* W_ih1 = (const float*)d_in[7];
    const float* W_hh1 = (const float*)d_in[8];
    const float* b_ih1 = (const float*)d_in[9];
    const float* b_hh1 = (const float*)d_in[10];
    const float* W_fc  = (const float*)d_in[11];
    const float* b_fc  = (const float*)d_in[12];

    float *hseq0, *h1last;
    cudaGetSymbolAddress((void**)&hseq0,  g_hseq0);
    cudaGetSymbolAddress((void**)&h1last, g_h1last);

    const int smem_l0 = (16 * (II + HH) + 2 * 64 * INPITCH + 1024 + 16) * sizeof(float);
    const int smem_l1 = (16 * (HH + HH) + 2 * 64 * INPITCH + 1024 + 16) * sizeof(float);
    cudaFuncSetAttribute((const void*)lstm_rec_kernel,
                         cudaFuncAttributeMaxDynamicSharedMemorySize, smem_l1);

    lstm_rec_kernel<<<NBLK, NTHR, smem_l0>>>(
        x, W_ih0, W_hh0, b_ih0, b_hh0,
        h0 + 0 * BB * HH, c0 + 0 * BB * HH,
        hseq0, nullptr, II);

    lstm_rec_kernel<<<NBLK, NTHR, smem_l1>>>(
        hseq0, W_ih1, W_hh1, b_ih1, b_hh1,
        h0 + 1 * BB * HH, c0 + 1 * BB * HH,
        nullptr, h1last, HH);

    fc_kernel<<<(BB * CC) / 256, 256>>>(h1last, W_fc, b_fc, (float*)d_out);
}

// round 4
// speedup vs baseline: 1.5533x; 1.3588x over previous
#include <cuda_runtime.h>
#include <math.h>

#define BB 64
#define TT 512
#define II 256
#define HH 512
#define CC 128

#define NBLK 128
#define NTHR 512
#define CHUNK 128
#define INPITCH 132

#define K0 (II + HH)      // 768
#define K1 (HH + HH)      // 1024
#define NCH0 (K0 / CHUNK) // 6
#define NCH1 (K1 / CHUNK) // 8
#define NWAVE (TT + 1)    // 513

typedef unsigned long long ull;

// ---------------- device scratch ----------------
__device__ float g_h0buf[2][BB * HH];
__device__ float g_h1buf[2][BB * HH];
__device__ float g_h1last[BB * HH];
__device__ unsigned g_ctr;   // zero-init; self-resets at layer end

// ---------------- primitives ----------------
__device__ __forceinline__ void cp_async16_cg(void* smem_dst, const void* gsrc) {
    unsigned s = (unsigned)__cvta_generic_to_shared(smem_dst);
    asm volatile("cp.async.cg.shared.global [%0], [%1], 16;\n" :: "r"(s), "l"(gsrc) : "memory");
}
__device__ __forceinline__ void cp_commit() {
    asm volatile("cp.async.commit_group;\n" ::: "memory");
}
template <int N>
__device__ __forceinline__ void cp_wait() {
    asm volatile("cp.async.wait_group %0;\n" :: "n"(N) : "memory");
}
__device__ __forceinline__ ull ffma2(ull a, ull b, ull c) {
    ull d;
    asm("fma.rn.f32x2 %0, %1, %2, %3;" : "=l"(d) : "l"(a), "l"(b), "l"(c));
    return d;
}
__device__ __forceinline__ float2 unpack2(ull v) {
    float2 f;
    asm("mov.b64 {%0, %1}, %2;" : "=f"(f.x), "=f"(f.y) : "l"(v));
    return f;
}
__device__ __forceinline__ void bar_arrive(unsigned* ctr, unsigned finalv) {
    unsigned old;
    asm volatile("atom.release.gpu.global.add.u32 %0, [%1], %2;"
                 : "=r"(old) : "l"(ctr), "r"(1u) : "memory");
    if (old == finalv - 1u) {
        asm volatile("st.relaxed.gpu.global.u32 [%0], %1;" :: "l"(ctr), "r"(0u) : "memory");
    }
}
__device__ __forceinline__ void bar_wait(unsigned* ctr, unsigned target) {
    unsigned v;
    do {
        asm volatile("ld.acquire.gpu.global.u32 %0, [%1];" : "=r"(v) : "l"(ctr) : "memory");
    } while (v < target);
}
__device__ __forceinline__ float sigmoidf_(float x) {
    return 1.0f / (1.0f + __expf(-x));
}

// ---------------- inner GEMM chunk: 8 gate rows x 2 batch rows per thread ----------------
template <int KTOT>
__device__ __forceinline__ void compute_chunk(ull* accA, ull* accB,
    const float* __restrict__ ins0, const float* __restrict__ ins1,
    const float* __restrict__ wbase)
{
    #pragma unroll
    for (int k = 0; k < 16; k += 4) {
        ulonglong2 xa = *(const ulonglong2*)(ins0 + k);
        ulonglong2 xb = *(const ulonglong2*)(ins1 + k);
        #pragma unroll
        for (int t4 = 0; t4 < 4; t4++) {
            #pragma unroll
            for (int cc = 0; cc < 2; cc++) {
                ulonglong2 wv = *(const ulonglong2*)(wbase + (t4 * 4 + cc) * KTOT + k);
                int j = t4 * 2 + cc;
                accA[j] = ffma2(xa.x, wv.x, accA[j]);
                accA[j] = ffma2(xa.y, wv.y, accA[j]);
                accB[j] = ffma2(xb.x, wv.x, accB[j]);
                accB[j] = ffma2(xb.y, wv.y, accB[j]);
            }
        }
    }
}

// ---------------- epilogue: k-split combine + gates + state update ----------------
__device__ __forceinline__ void epilogue(
    ull* accA, ull* accB, float* pex, const float* bias16,
    int r2, int g2, int ks, int colbase,
    float& cA0, float& cA1, float& cB0, float& cB1,
    float* __restrict__ hout, float* __restrict__ hlast)
{
    float vA[8], vB[8];
    #pragma unroll
    for (int j = 0; j < 8; j++) {
        float2 fa = unpack2(accA[j]); vA[j] = fa.x + fa.y;
        float2 fb = unpack2(accB[j]); vB[j] = fb.x + fb.y;
    }
    int cid = g2 * 32 + r2;
    if (ks) {
        float* d = pex + (ks - 1) * 1024 + cid * 16;
        *(float4*)(d + 0)  = make_float4(vA[0], vA[1], vA[2], vA[3]);
        *(float4*)(d + 4)  = make_float4(vA[4], vA[5], vA[6], vA[7]);
        *(float4*)(d + 8)  = make_float4(vB[0], vB[1], vB[2], vB[3]);
        *(float4*)(d + 12) = make_float4(vB[4], vB[5], vB[6], vB[7]);
    }
    __syncthreads();
    if (!ks) {
        #pragma unroll
        for (int q = 0; q < 7; q++) {
            const float* sp = pex + q * 1024 + cid * 16;
            float4 a0 = *(const float4*)(sp + 0);
            float4 a1 = *(const float4*)(sp + 4);
            float4 b0 = *(const float4*)(sp + 8);
            float4 b1 = *(const float4*)(sp + 12);
            vA[0] += a0.x; vA[1] += a0.y; vA[2] += a0.z; vA[3] += a0.w;
            vA[4] += a1.x; vA[5] += a1.y; vA[6] += a1.z; vA[7] += a1.w;
            vB[0] += b0.x; vB[1] += b0.y; vB[2] += b0.z; vB[3] += b0.w;
            vB[4] += b1.x; vB[5] += b1.y; vB[6] += b1.z; vB[7] += b1.w;
        }
        #pragma unroll
        for (int cc = 0; cc < 2; cc++) {
            float bi = bias16[0 * 4 + 2 * g2 + cc];
            float bf = bias16[1 * 4 + 2 * g2 + cc];
            float bg = bias16[2 * 4 + 2 * g2 + cc];
            float bo = bias16[3 * 4 + 2 * g2 + cc];
            int col = colbase + cc;
            // batch row r2
            {
                float iv = sigmoidf_(vA[0 + cc] + bi);
                float fv = sigmoidf_(vA[2 + cc] + bf);
                float gv = tanhf   (vA[4 + cc] + bg);
                float ov = sigmoidf_(vA[6 + cc] + bo);
                float& ca = cc ? cA1 : cA0;
                ca = fv * ca + iv * gv;
                float hv = ov * tanhf(ca);
                hout[r2 * HH + col] = hv;
                if (hlast) hlast[r2 * HH + col] = hv;
            }
            // batch row r2+32
            {
                float iv = sigmoidf_(vB[0 + cc] + bi);
                float fv = sigmoidf_(vB[2 + cc] + bf);
                float gv = tanhf   (vB[4 + cc] + bg);
                float ov = sigmoidf_(vB[6 + cc] + bo);
                float& cb = cc ? cB1 : cB0;
                cb = fv * cb + iv * gv;
                float hv = ov * tanhf(cb);
                hout[(r2 + 32) * HH + col] = hv;
                if (hlast) hlast[(r2 + 32) * HH + col] = hv;
            }
        }
    }
    __syncthreads();   // pex reuse guard
}

// ---------------- fused two-layer wavefront LSTM ----------------
__global__ void __launch_bounds__(NTHR, 1) lstm_fused_kernel(
    const float* __restrict__ xin,
    const float* __restrict__ W_ih0, const float* __restrict__ W_hh0,
    const float* __restrict__ b_ih0, const float* __restrict__ b_hh0,
    const float* __restrict__ W_ih1, const float* __restrict__ W_hh1,
    const float* __restrict__ b_ih1, const float* __restrict__ b_hh1,
    const float* __restrict__ h0, const float* __restrict__ c0)
{
    const int tid = threadIdx.x;
    const int blk = blockIdx.x;
    const int r2 = tid & 31;
    const int g2 = (tid >> 5) & 1;
    const int ks = tid >> 6;       // 0..7
    const int koff = ks * 16;
    const int colbase = blk * 4 + g2 * 2;
    const unsigned finalv = (unsigned)NBLK * (NWAVE + 1);

    extern __shared__ float smem[];
    float* W0_s   = smem;                      // [16][768]
    float* W1_s   = W0_s + 16 * K0;            // [16][1024]
    float* in_s   = W1_s + 16 * K1;            // [2][64][132]
    float* pex    = in_s + 2 * 64 * INPITCH;   // [7][1024]
    float* bias_s = pex + 7 * 1024;            // [2][16]

    // --- weights resident in SMEM for both layers ---
    for (int idx = tid; idx < 16 * K0; idx += NTHR) {
        int l = idx / K0, k = idx - l * K0;
        int g = (l >> 2) * HH + blk * 4 + (l & 3);
        W0_s[idx] = (k < II) ? W_ih0[(size_t)g * II + k] : W_hh0[(size_t)g * HH + (k - II)];
    }
    for (int idx = tid; idx < 16 * K1; idx += NTHR) {
        int l = idx / K1, k = idx - l * K1;
        int g = (l >> 2) * HH + blk * 4 + (l & 3);
        W1_s[idx] = (k < HH) ? W_ih1[(size_t)g * HH + k] : W_hh1[(size_t)g * HH + (k - HH)];
    }
    if (tid < 32) {
        int l = tid & 15;
        int g = (l >> 2) * HH + blk * 4 + (l & 3);
        bias_s[tid] = (tid < 16) ? (b_ih0[g] + b_hh0[g]) : (b_ih1[g] + b_hh1[g]);
    }

    // --- init h buffers (each block writes its own 256-elem slice) ---
    if (tid < 256) {
        int i = blk * 256 + tid;
        g_h0buf[0][i] = h0[i];                 // layer0 h init -> parity 0
        g_h1buf[1][i] = h0[BB * HH + i];       // layer1 h init -> parity 1
    }

    // --- c state (combiner threads ks==0 use them) ---
    float c0A0 = c0[r2 * HH + colbase],        c0A1 = c0[r2 * HH + colbase + 1];
    float c0B0 = c0[(r2 + 32) * HH + colbase], c0B1 = c0[(r2 + 32) * HH + colbase + 1];
    float c1A0 = c0[BB * HH + r2 * HH + colbase];
    float c1A1 = c0[BB * HH + r2 * HH + colbase + 1];
    float c1B0 = c0[BB * HH + (r2 + 32) * HH + colbase];
    float c1B1 = c0[BB * HH + (r2 + 32) * HH + colbase + 1];

    __syncthreads();
    if (tid == 0) bar_arrive(&g_ctr, finalv);

    #pragma unroll 1
    for (int s = 0; s < NWAVE; s++) {
        const int p = s & 1;
        const float* h0rd = g_h0buf[p];
        const float* h1rd = g_h1buf[p];
        float* h0wr = g_h0buf[p ^ 1];
        float* h1wr = g_h1buf[p ^ 1];
        int waited = 0;
        const unsigned wtarget = (unsigned)(s + 1) * NBLK;

        auto stage0 = [&](int ch) {
            int kbase = ch * CHUNK;
            float* dst = in_s + (ch & 1) * (64 * INPITCH);
            #pragma unroll
            for (int i = 0; i < 4; i++) {
                int idx = tid + i * NTHR;
                int row = idx >> 5;
                int k4 = (idx & 31) << 2;
                int kk = kbase + k4;
                const float* src = (kk < II)
                    ? xin + ((size_t)row * TT + s) * II + kk
                    : h0rd + row * HH + (kk - II);
                cp_async16_cg(dst + row * INPITCH + k4, src);
            }
            cp_commit();
        };
        auto stage1 = [&](int ch) {
            int kbase = ch * CHUNK;
            float* dst = in_s + (ch & 1) * (64 * INPITCH);
            #pragma unroll
            for (int i = 0; i < 4; i++) {
                int idx = tid + i * NTHR;
                int row = idx >> 5;
                int k4 = (idx & 31) << 2;
                int kk = kbase + k4;
                const float* src = (kk < HH)
                    ? h0rd + row * HH + kk
                    : h1rd + row * HH + (kk - HH);
                cp_async16_cg(dst + row * INPITCH + k4, src);
            }
            cp_commit();
        };

        // ---------- layer 0, step s ----------
        if (s < TT) {
            ull accA[8] = {0,0,0,0,0,0,0,0};
            ull accB[8] = {0,0,0,0,0,0,0,0};
            stage0(0);
            #pragma unroll 1
            for (int ch = 0; ch < NCH0; ch++) {
                if (ch + 1 < NCH0) {
                    if (ch + 1 == II / CHUNK && !waited) {  // first h-chunk: need prev wavefront
                        if (tid == 0) bar_wait(&g_ctr, wtarget);
                        __syncthreads();
                        waited = 1;
                    }
                    stage0(ch + 1);
                    cp_wait<1>();
                } else {
                    cp_wait<0>();
                }
                __syncthreads();
                const float* ins0 = in_s + (ch & 1) * (64 * INPITCH) + r2 * INPITCH + koff;
                compute_chunk<K0>(accA, accB, ins0, ins0 + 32 * INPITCH,
                                  W0_s + (2 * g2) * K0 + ch * CHUNK + koff);
                __syncthreads();
            }
            epilogue(accA, accB, pex, bias_s, r2, g2, ks, colbase,
                     c0A0, c0A1, c0B0, c0B1, h0wr, nullptr);
        }

        // ---------- layer 1, step s-1 ----------
        if (s >= 1) {
            if (!waited) {          // only when s==NWAVE-1 (L0 skipped)
                if (tid == 0) bar_wait(&g_ctr, wtarget);
                __syncthreads();
                waited = 1;
            }
            ull accA[8] = {0,0,0,0,0,0,0,0};
            ull accB[8] = {0,0,0,0,0,0,0,0};
            stage1(0);
            #pragma unroll 1
            for (int ch = 0; ch < NCH1; ch++) {
                if (ch + 1 < NCH1) {
                    stage1(ch + 1);
                    cp_wait<1>();
                } else {
                    cp_wait<0>();
                }
                __syncthreads();
                const float* ins0 = in_s + (ch & 1) * (64 * INPITCH) + r2 * INPITCH + koff;
                compute_chunk<K1>(accA, accB, ins0, ins0 + 32 * INPITCH,
                                  W1_s + (2 * g2) * K1 + ch * CHUNK + koff);
                __syncthreads();
            }
            epilogue(accA, accB, pex, bias_s + 16, r2, g2, ks, colbase,
                     c1A0, c1A1, c1B0, c1B1, h1wr,
                     (s == TT) ? g_h1last : nullptr);
        }

        if (tid == 0) bar_arrive(&g_ctr, finalv);
    }
}

// ---------------- final linear head ----------------
__global__ void fc_kernel(const float* __restrict__ W,   // [C,H]
                          const float* __restrict__ b,   // [C]
                          float* __restrict__ out)       // [B,C]
{
    int idx = blockIdx.x * blockDim.x + threadIdx.x;     // 8192
    int r = idx >> 7;
    int c = idx & 127;
    const float* hr = g_h1last + r * HH;
    const float* wc = W + c * HH;
    float acc = b[c];
    #pragma unroll 4
    for (int k = 0; k < HH; k += 4) {
        float4 hv = *(const float4*)(hr + k);
        float4 wv = *(const float4*)(wc + k);
        acc += hv.x * wv.x + hv.y * wv.y + hv.z * wv.z + hv.w * wv.w;
    }
    out[idx] = acc;
}

// ---------------- launch ----------------
extern "C" void kernel_launch(void* const* d_in, const int* in_sizes, int n_in,
                              void* d_out, int out_size) {
    const float* x     = (const float*)d_in[0];
    const float* h0    = (const float*)d_in[1];
    const float* c0    = (const float*)d_in[2];
    const float* W_ih0 = (const float*)d_in[3];
    const float* W_hh0 = (const float*)d_in[4];
    const float* b_ih0 = (const float*)d_in[5];
    const float* b_hh0 = (const float*)d_in[6];
    const float* W_ih1 = (const float*)d_in[7];
    const float* W_hh1 = (const float*)d_in[8];
    const float* b_ih1 = (const float*)d_in[9];
    const float* b_hh1 = (const float*)d_in[10];
    const float* W_fc  = (const float*)d_in[11];
    const float* b_fc  = (const float*)d_in[12];

    const int smem_bytes =
        (16 * K0 + 16 * K1 + 2 * 64 * INPITCH + 7 * 1024 + 32) * sizeof(float);
    cudaFuncSetAttribute((const void*)lstm_fused_kernel,
                         cudaFuncAttributeMaxDynamicSharedMemorySize, smem_bytes);

    lstm_fused_kernel<<<NBLK, NTHR, smem_bytes>>>(
        x, W_ih0, W_hh0, b_ih0, b_hh0,
        W_ih1, W_hh1, b_ih1, b_hh1,
        h0, c0);

    fc_kernel<<<(BB * CC) / 256, 256>>>(W_fc, b_fc, (float*)d_out);
}